// round 1
// baseline (speedup 1.0000x reference)
#include <cuda_runtime.h>
#include <math.h>

#define UC 100000
#define IC 50000
#define NC 150000
#define DD 64
#define EC 3000000
#define BB 8192
#define NEG_SLOPE 0.2f

// ---------------- device scratch (no runtime allocation allowed) ----------------
__device__ float g_ego[NC * DD];    // current (un-normalized) embeddings
__device__ float g_side[NC * DD];   // SpMM output
__device__ float g_n1[NC * DD];     // normalized layer-1 embeddings
__device__ float g_n2[NC * DD];     // normalized layer-2 embeddings
__device__ int   g_rowptr[NC + 1];
__device__ int   g_cnt[NC];
__device__ int   g_ecol[EC];
__device__ float g_eval[EC];
__device__ double g_acc[2];         // [0]=sum softplus, [1]=sum squares (reg)

// ---------------- init: concat embeddings, zero counters/accumulators ----------
__global__ void k_init(const float* __restrict__ uemb, const float* __restrict__ iemb) {
    int i = blockIdx.x * blockDim.x + threadIdx.x;
    if (i < NC * DD) g_ego[i] = (i < UC * DD) ? uemb[i] : iemb[i - UC * DD];
    if (i < NC) g_cnt[i] = 0;
    if (i < 2) g_acc[i] = 0.0;
}

// ---------------- CSR build: histogram -> scan -> scatter ----------------------
__global__ void k_hist(const int* __restrict__ rows) {
    int stride = gridDim.x * blockDim.x;
    for (int e = blockIdx.x * blockDim.x + threadIdx.x; e < EC; e += stride)
        atomicAdd(&g_cnt[rows[e]], 1);
}

__global__ void k_scan() {
    __shared__ int s[1024];
    int t = threadIdx.x;
    const int CH = (NC + 1023) / 1024;  // 147
    int beg = t * CH;
    int end = beg + CH;
    if (beg > NC) beg = NC;
    if (end > NC) end = NC;
    int sum = 0;
    for (int i = beg; i < end; i++) sum += g_cnt[i];
    s[t] = sum;
    __syncthreads();
    // Hillis-Steele inclusive scan over 1024 chunk sums
    for (int o = 1; o < 1024; o <<= 1) {
        int v = (t >= o) ? s[t - o] : 0;
        __syncthreads();
        s[t] += v;
        __syncthreads();
    }
    int run = s[t] - sum;  // exclusive prefix of this chunk
    for (int i = beg; i < end; i++) {
        int c = g_cnt[i];
        g_rowptr[i] = run;
        run += c;
        g_cnt[i] = 0;  // reset for scatter pass
    }
    if (t == 1023) g_rowptr[NC] = s[1023];
}

__global__ void k_scatter(const int* __restrict__ rows, const int* __restrict__ cols,
                          const float* __restrict__ vals) {
    int stride = gridDim.x * blockDim.x;
    for (int e = blockIdx.x * blockDim.x + threadIdx.x; e < EC; e += stride) {
        int r = rows[e];
        int p = g_rowptr[r] + atomicAdd(&g_cnt[r], 1);
        g_ecol[p] = cols[e];
        g_eval[p] = vals[e];
    }
}

// ---------------- SpMM: one warp per row, atomic-free ---------------------------
__global__ void k_spmm() {
    int w = (blockIdx.x * blockDim.x + threadIdx.x) >> 5;
    int lane = threadIdx.x & 31;
    if (w >= NC) return;
    int s = g_rowptr[w], e = g_rowptr[w + 1];
    float a0 = 0.f, a1 = 0.f;
    for (int i = s; i < e; i++) {
        int c = __ldg(&g_ecol[i]);
        float v = __ldg(&g_eval[i]);
        const float* xr = g_ego + (size_t)c * DD;
        a0 += v * __ldg(&xr[lane]);
        a1 += v * __ldg(&xr[lane + 32]);
    }
    g_side[(size_t)w * DD + lane] = a0;
    g_side[(size_t)w * DD + lane + 32] = a1;
}

// ---------------- fused dual GEMM + leaky_relu + bias + row-normalize ----------
// ego_new = leaky(side @ Wg + bg) @ Wm + bm ; also writes ego_new/||ego_new||
__global__ __launch_bounds__(256) void k_gemm(const float* __restrict__ Wg,
                                              const float* __restrict__ bg,
                                              const float* __restrict__ Wm,
                                              const float* __restrict__ bm,
                                              int layer) {
    __shared__ float sX[DD][DD + 1];  // [k][row] transposed tile
    __shared__ float sW[DD][DD];      // [k][c]
    int tid = threadIdx.x;
    int rowBase = blockIdx.x * 64;

    for (int i = tid; i < DD * DD; i += 256) sW[i >> 6][i & 63] = Wg[i];
    for (int i = tid; i < 64 * DD; i += 256) {
        int r = i >> 6, k = i & 63;
        int gr = rowBase + r;
        sX[k][r] = (gr < NC) ? g_side[(size_t)gr * DD + k] : 0.f;
    }
    __syncthreads();

    int ct = tid & 15, rt = tid >> 4;
    int c0 = ct * 4, r0 = rt * 4;

    float acc[4][4];
#pragma unroll
    for (int i = 0; i < 4; i++)
#pragma unroll
        for (int j = 0; j < 4; j++) acc[i][j] = 0.f;

#pragma unroll 8
    for (int k = 0; k < DD; k++) {
        float a[4], b[4];
#pragma unroll
        for (int i = 0; i < 4; i++) a[i] = sX[k][r0 + i];
#pragma unroll
        for (int j = 0; j < 4; j++) b[j] = sW[k][c0 + j];
#pragma unroll
        for (int i = 0; i < 4; i++)
#pragma unroll
            for (int j = 0; j < 4; j++) acc[i][j] += a[i] * b[j];
    }

    // bias + leaky relu
    float t[4][4];
#pragma unroll
    for (int j = 0; j < 4; j++) {
        float bv = __ldg(&bg[c0 + j]);
#pragma unroll
        for (int i = 0; i < 4; i++) {
            float v = acc[i][j] + bv;
            t[i][j] = (v > 0.f) ? v : NEG_SLOPE * v;
        }
    }
    __syncthreads();  // everyone done reading sX / sW (gemm1)

    // overwrite shared: sW <- Wm, sX <- T (transposed)
    for (int i = tid; i < DD * DD; i += 256) sW[i >> 6][i & 63] = Wm[i];
#pragma unroll
    for (int i = 0; i < 4; i++)
#pragma unroll
        for (int j = 0; j < 4; j++) sX[c0 + j][r0 + i] = t[i][j];
    __syncthreads();

#pragma unroll
    for (int i = 0; i < 4; i++)
#pragma unroll
        for (int j = 0; j < 4; j++) acc[i][j] = 0.f;

#pragma unroll 8
    for (int k = 0; k < DD; k++) {
        float a[4], b[4];
#pragma unroll
        for (int i = 0; i < 4; i++) a[i] = sX[k][r0 + i];
#pragma unroll
        for (int j = 0; j < 4; j++) b[j] = sW[k][c0 + j];
#pragma unroll
        for (int i = 0; i < 4; i++)
#pragma unroll
            for (int j = 0; j < 4; j++) acc[i][j] += a[i] * b[j];
    }

    float y[4][4];
#pragma unroll
    for (int j = 0; j < 4; j++) {
        float bv = __ldg(&bm[c0 + j]);
#pragma unroll
        for (int i = 0; i < 4; i++) y[i][j] = acc[i][j] + bv;
    }

    float* nbuf = (layer == 0) ? g_n1 : g_n2;
#pragma unroll
    for (int i = 0; i < 4; i++) {
        float ss = y[i][0] * y[i][0] + y[i][1] * y[i][1] + y[i][2] * y[i][2] + y[i][3] * y[i][3];
        // reduce across the 16 ct-lanes sharing this row group (width-16 butterfly)
#pragma unroll
        for (int o = 8; o > 0; o >>= 1) ss += __shfl_xor_sync(0xffffffffu, ss, o, 16);
        float inv = 1.f / fmaxf(sqrtf(ss), 1e-12f);
        int gr = rowBase + r0 + i;
        if (gr < NC) {
            float4 v4 = make_float4(y[i][0], y[i][1], y[i][2], y[i][3]);
            *(float4*)&g_ego[(size_t)gr * DD + c0] = v4;
            float4 nv = make_float4(y[i][0] * inv, y[i][1] * inv, y[i][2] * inv, y[i][3] * inv);
            *(float4*)&nbuf[(size_t)gr * DD + c0] = nv;
        }
    }
}

// ---------------- BPR scoring + regularization ---------------------------------
__global__ void k_score(const int* __restrict__ user, const int* __restrict__ pos,
                        const int* __restrict__ neg, const float* __restrict__ uemb,
                        const float* __restrict__ iemb) {
    __shared__ float sb[8];
    __shared__ float sr[8];
    int tid = threadIdx.x;
    int wid = tid >> 5, lane = tid & 31;
    int b = blockIdx.x * 8 + wid;
    float sp = 0.f, rg = 0.f;
    if (b < BB) {
        int uu = user[b], pp = pos[b], nn = neg[b];
        const float* u0 = uemb + (size_t)uu * DD;
        const float* p0 = iemb + (size_t)pp * DD;
        const float* n0 = iemb + (size_t)nn * DD;
        const float* u1 = g_n1 + (size_t)uu * DD;
        const float* p1 = g_n1 + (size_t)(UC + pp) * DD;
        const float* n1 = g_n1 + (size_t)(UC + nn) * DD;
        const float* u2 = g_n2 + (size_t)uu * DD;
        const float* p2 = g_n2 + (size_t)(UC + pp) * DD;
        const float* n2 = g_n2 + (size_t)(UC + nn) * DD;
        float ps = 0.f, ns = 0.f;
#pragma unroll
        for (int h = 0; h < 2; h++) {
            int d = lane + 32 * h;
            float ue = u0[d], pe = p0[d], ne = n0[d];
            rg += ue * ue + pe * pe + ne * ne;
            ps += ue * pe;
            ns += ue * ne;
            float a1 = u1[d]; ps += a1 * p1[d]; ns += a1 * n1[d];
            float a2 = u2[d]; ps += a2 * p2[d]; ns += a2 * n2[d];
        }
#pragma unroll
        for (int o = 16; o > 0; o >>= 1) {
            ps += __shfl_xor_sync(0xffffffffu, ps, o);
            ns += __shfl_xor_sync(0xffffffffu, ns, o);
            rg += __shfl_xor_sync(0xffffffffu, rg, o);
        }
        float x = ns - ps;
        sp = fmaxf(x, 0.f) + log1pf(expf(-fabsf(x)));  // stable softplus
    }
    if (lane == 0) { sb[wid] = sp; sr[wid] = rg; }
    __syncthreads();
    if (tid == 0) {
        float s1 = 0.f, s2 = 0.f;
        for (int i = 0; i < 8; i++) { s1 += sb[i]; s2 += sr[i]; }
        atomicAdd(&g_acc[0], (double)s1);
        atomicAdd(&g_acc[1], (double)s2);
    }
}

__global__ void k_final(float* out) {
    out[0] = (float)(g_acc[0] / (double)BB);
    out[1] = (float)(0.0001 * 0.5 * g_acc[1] / (double)BB);
}

// ---------------- launch -------------------------------------------------------
extern "C" void kernel_launch(void* const* d_in, const int* in_sizes, int n_in,
                              void* d_out, int out_size) {
    (void)in_sizes; (void)n_in; (void)out_size;
    const int*   user = (const int*)d_in[0];
    const int*   pos  = (const int*)d_in[1];
    const int*   neg  = (const int*)d_in[2];
    const int*   rows = (const int*)d_in[3];
    const int*   cols = (const int*)d_in[4];
    const float* vals = (const float*)d_in[5];
    const float* uemb = (const float*)d_in[6];
    const float* iemb = (const float*)d_in[7];
    const float* Wg0  = (const float*)d_in[8];
    const float* bg0  = (const float*)d_in[9];
    const float* Wm0  = (const float*)d_in[10];
    const float* bm0  = (const float*)d_in[11];
    const float* Wg1  = (const float*)d_in[12];
    const float* bg1  = (const float*)d_in[13];
    const float* Wm1  = (const float*)d_in[14];
    const float* bm1  = (const float*)d_in[15];
    float* out = (float*)d_out;

    k_init<<<(NC * DD + 255) / 256, 256>>>(uemb, iemb);
    k_hist<<<2048, 256>>>(rows);
    k_scan<<<1, 1024>>>();
    k_scatter<<<2048, 256>>>(rows, cols, vals);

    int spmm_blocks = (NC * 32 + 255) / 256;
    int gemm_blocks = (NC + 63) / 64;

    // layer 0
    k_spmm<<<spmm_blocks, 256>>>();
    k_gemm<<<gemm_blocks, 256>>>(Wg0, bg0, Wm0, bm0, 0);
    // layer 1
    k_spmm<<<spmm_blocks, 256>>>();
    k_gemm<<<gemm_blocks, 256>>>(Wg1, bg1, Wm1, bm1, 1);

    k_score<<<(BB + 7) / 8, 256>>>(user, pos, neg, uemb, iemb);
    k_final<<<1, 1>>>(out);
}

// round 2
// speedup vs baseline: 1.2087x; 1.2087x over previous
#include <cuda_runtime.h>
#include <math.h>

#define UC 100000
#define IC 50000
#define NC 150000
#define DD 64
#define EC 3000000
#define BB 8192
#define NEG_SLOPE 0.2f

typedef unsigned long long u64;

// ---------------- packed f32x2 helpers (PTX-only; doubles fp32 FMA rate) -------
__device__ __forceinline__ u64 pk2(float x, float y) {
    u64 r; asm("mov.b64 %0,{%1,%2};" : "=l"(r) : "f"(x), "f"(y)); return r;
}
__device__ __forceinline__ void upk2(u64 v, float& x, float& y) {
    asm("mov.b64 {%0,%1},%2;" : "=f"(x), "=f"(y) : "l"(v));
}
__device__ __forceinline__ u64 fma2(u64 a, u64 b, u64 c) {
    u64 d; asm("fma.rn.f32x2 %0,%1,%2,%3;" : "=l"(d) : "l"(a), "l"(b), "l"(c)); return d;
}

// ---------------- device scratch ------------------------------------------------
__device__ float  g_ego[NC * DD];    // layer-0 output (input to spmm1)
__device__ float  g_side[NC * DD];   // SpMM output
__device__ float  g_n1[NC * DD];     // normalized layer-1 embeddings
__device__ float  g_n2[NC * DD];     // normalized layer-2 embeddings
__device__ int    g_rowptr[NC + 1];
__device__ int    g_cnt[NC];
__device__ float2 g_epk[EC];         // packed (col_as_float, val)
__device__ double g_acc[2];

// ---------------- zero counters/accumulators -----------------------------------
__global__ void k_zero() {
    int i = blockIdx.x * blockDim.x + threadIdx.x;
    if (i < NC) g_cnt[i] = 0;
    if (i < 2) g_acc[i] = 0.0;
}

// ---------------- CSR build ------------------------------------------------------
__global__ void k_hist(const int* __restrict__ rows) {
    int stride = gridDim.x * blockDim.x;
    const int4* r4 = (const int4*)rows;
    for (int e = blockIdx.x * blockDim.x + threadIdx.x; e < EC / 4; e += stride) {
        int4 v = r4[e];
        atomicAdd(&g_cnt[v.x], 1);
        atomicAdd(&g_cnt[v.y], 1);
        atomicAdd(&g_cnt[v.z], 1);
        atomicAdd(&g_cnt[v.w], 1);
    }
}

__global__ void k_scan() {
    __shared__ int s[1024];
    int t = threadIdx.x;
    const int CH = (NC + 1023) / 1024;
    int beg = t * CH, end = beg + CH;
    if (beg > NC) beg = NC;
    if (end > NC) end = NC;
    int sum = 0;
    for (int i = beg; i < end; i++) sum += g_cnt[i];
    s[t] = sum;
    __syncthreads();
    for (int o = 1; o < 1024; o <<= 1) {
        int v = (t >= o) ? s[t - o] : 0;
        __syncthreads();
        s[t] += v;
        __syncthreads();
    }
    int run = s[t] - sum;
    for (int i = beg; i < end; i++) {
        int c = g_cnt[i];
        g_rowptr[i] = run;
        run += c;
        g_cnt[i] = 0;
    }
    if (t == 1023) g_rowptr[NC] = s[1023];
}

__global__ void k_scatter(const int* __restrict__ rows, const int* __restrict__ cols,
                          const float* __restrict__ vals) {
    int stride = gridDim.x * blockDim.x;
    for (int e = blockIdx.x * blockDim.x + threadIdx.x; e < EC; e += stride) {
        int r = rows[e];
        int p = g_rowptr[r] + atomicAdd(&g_cnt[r], 1);
        g_epk[p] = make_float2(__int_as_float(cols[e]), vals[e]);
    }
}

// ---------------- SpMM: warp per row, atomic-free, packed f32x2 -----------------
__global__ void k_spmm(const float* __restrict__ bu, const float* __restrict__ bi) {
    int w = (blockIdx.x * blockDim.x + threadIdx.x) >> 5;
    int lane = threadIdx.x & 31;
    if (w >= NC) return;
    int s = g_rowptr[w], e = g_rowptr[w + 1];
    u64 a0 = 0ull, a1 = 0ull;
    int i = s;
    for (; i + 1 < e; i += 2) {
        float2 p0 = g_epk[i], p1 = g_epk[i + 1];
        int c0 = __float_as_int(p0.x), c1 = __float_as_int(p1.x);
        const float* x0 = (c0 < UC) ? bu + (size_t)c0 * DD : bi + (size_t)(c0 - UC) * DD;
        const float* x1 = (c1 < UC) ? bu + (size_t)c1 * DD : bi + (size_t)(c1 - UC) * DD;
        u64 v0 = *(const u64*)(x0 + lane * 2);
        u64 v1 = *(const u64*)(x1 + lane * 2);
        a0 = fma2(pk2(p0.y, p0.y), v0, a0);
        a1 = fma2(pk2(p1.y, p1.y), v1, a1);
    }
    if (i < e) {
        float2 p0 = g_epk[i];
        int c0 = __float_as_int(p0.x);
        const float* x0 = (c0 < UC) ? bu + (size_t)c0 * DD : bi + (size_t)(c0 - UC) * DD;
        u64 v0 = *(const u64*)(x0 + lane * 2);
        a0 = fma2(pk2(p0.y, p0.y), v0, a0);
    }
    float s0x, s0y, s1x, s1y;
    upk2(a0, s0x, s0y);
    upk2(a1, s1x, s1y);
    *(float2*)&g_side[(size_t)w * DD + lane * 2] = make_float2(s0x + s1x, s0y + s1y);
}

// ---------------- fused dual GEMM + leaky + bias + row-normalize ----------------
// tile: 128 rows x 64 cols, 256 threads, each 8 rows x 4 cols via f32x2 pairs
#define PADX 132
__global__ __launch_bounds__(256) void k_gemm(const float* __restrict__ Wg,
                                              const float* __restrict__ bg,
                                              const float* __restrict__ Wm,
                                              const float* __restrict__ bm,
                                              int layer) {
    __shared__ float sX[DD][PADX];   // [k][row]
    __shared__ float sW[DD][DD];     // [k][c]
    int tid = threadIdx.x;
    int rowBase = blockIdx.x * 128;

    // load W_gcn (flat float4 copy)
    for (int i = tid; i < DD * DD / 4; i += 256)
        ((float4*)sW)[i] = ((const float4*)Wg)[i];
    // load X tile transposed: thread i -> row r = i>>4, k4 = (i&15)*4
    for (int i = tid; i < 128 * 16; i += 256) {
        int r = i >> 4, k4 = (i & 15) * 4;
        int gr = rowBase + r;
        float4 v = (gr < NC) ? *(const float4*)&g_side[(size_t)gr * DD + k4]
                             : make_float4(0.f, 0.f, 0.f, 0.f);
        sX[k4][r] = v.x; sX[k4 + 1][r] = v.y; sX[k4 + 2][r] = v.z; sX[k4 + 3][r] = v.w;
    }
    __syncthreads();

    int ct = tid & 15, rt = tid >> 4;
    int c0 = ct * 4, r0 = rt * 8;

    u64 acc[4][4];
#pragma unroll
    for (int p = 0; p < 4; p++)
#pragma unroll
        for (int j = 0; j < 4; j++) acc[p][j] = 0ull;

#pragma unroll 8
    for (int k = 0; k < DD; k++) {
        ulonglong2 A0 = *(const ulonglong2*)&sX[k][r0];      // row pairs 0,1
        ulonglong2 A1 = *(const ulonglong2*)&sX[k][r0 + 4];  // row pairs 2,3
        float4 bv = *(const float4*)&sW[k][c0];
        u64 B0 = pk2(bv.x, bv.x), B1 = pk2(bv.y, bv.y);
        u64 B2 = pk2(bv.z, bv.z), B3 = pk2(bv.w, bv.w);
        acc[0][0] = fma2(A0.x, B0, acc[0][0]); acc[0][1] = fma2(A0.x, B1, acc[0][1]);
        acc[0][2] = fma2(A0.x, B2, acc[0][2]); acc[0][3] = fma2(A0.x, B3, acc[0][3]);
        acc[1][0] = fma2(A0.y, B0, acc[1][0]); acc[1][1] = fma2(A0.y, B1, acc[1][1]);
        acc[1][2] = fma2(A0.y, B2, acc[1][2]); acc[1][3] = fma2(A0.y, B3, acc[1][3]);
        acc[2][0] = fma2(A1.x, B0, acc[2][0]); acc[2][1] = fma2(A1.x, B1, acc[2][1]);
        acc[2][2] = fma2(A1.x, B2, acc[2][2]); acc[2][3] = fma2(A1.x, B3, acc[2][3]);
        acc[3][0] = fma2(A1.y, B0, acc[3][0]); acc[3][1] = fma2(A1.y, B1, acc[3][1]);
        acc[3][2] = fma2(A1.y, B2, acc[3][2]); acc[3][3] = fma2(A1.y, B3, acc[3][3]);
    }

    // bias + leaky relu -> t[8][4]
    float t[8][4];
#pragma unroll
    for (int p = 0; p < 4; p++)
#pragma unroll
        for (int j = 0; j < 4; j++) {
            float lo, hi;
            upk2(acc[p][j], lo, hi);
            float bv = __ldg(&bg[c0 + j]);
            lo += bv; hi += bv;
            t[2 * p][j]     = (lo > 0.f) ? lo : NEG_SLOPE * lo;
            t[2 * p + 1][j] = (hi > 0.f) ? hi : NEG_SLOPE * hi;
        }
    __syncthreads();

    // swap operands: sW <- Wm, sX <- t (transposed)
    for (int i = tid; i < DD * DD / 4; i += 256)
        ((float4*)sW)[i] = ((const float4*)Wm)[i];
#pragma unroll
    for (int i = 0; i < 8; i++)
#pragma unroll
        for (int j = 0; j < 4; j++) sX[c0 + j][r0 + i] = t[i][j];
    __syncthreads();

#pragma unroll
    for (int p = 0; p < 4; p++)
#pragma unroll
        for (int j = 0; j < 4; j++) acc[p][j] = 0ull;

#pragma unroll 8
    for (int k = 0; k < DD; k++) {
        ulonglong2 A0 = *(const ulonglong2*)&sX[k][r0];
        ulonglong2 A1 = *(const ulonglong2*)&sX[k][r0 + 4];
        float4 bv = *(const float4*)&sW[k][c0];
        u64 B0 = pk2(bv.x, bv.x), B1 = pk2(bv.y, bv.y);
        u64 B2 = pk2(bv.z, bv.z), B3 = pk2(bv.w, bv.w);
        acc[0][0] = fma2(A0.x, B0, acc[0][0]); acc[0][1] = fma2(A0.x, B1, acc[0][1]);
        acc[0][2] = fma2(A0.x, B2, acc[0][2]); acc[0][3] = fma2(A0.x, B3, acc[0][3]);
        acc[1][0] = fma2(A0.y, B0, acc[1][0]); acc[1][1] = fma2(A0.y, B1, acc[1][1]);
        acc[1][2] = fma2(A0.y, B2, acc[1][2]); acc[1][3] = fma2(A0.y, B3, acc[1][3]);
        acc[2][0] = fma2(A1.x, B0, acc[2][0]); acc[2][1] = fma2(A1.x, B1, acc[2][1]);
        acc[2][2] = fma2(A1.x, B2, acc[2][2]); acc[2][3] = fma2(A1.x, B3, acc[2][3]);
        acc[3][0] = fma2(A1.y, B0, acc[3][0]); acc[3][1] = fma2(A1.y, B1, acc[3][1]);
        acc[3][2] = fma2(A1.y, B2, acc[3][2]); acc[3][3] = fma2(A1.y, B3, acc[3][3]);
    }

    float y[8][4];
#pragma unroll
    for (int p = 0; p < 4; p++)
#pragma unroll
        for (int j = 0; j < 4; j++) {
            float lo, hi;
            upk2(acc[p][j], lo, hi);
            float bv = __ldg(&bm[c0 + j]);
            y[2 * p][j] = lo + bv;
            y[2 * p + 1][j] = hi + bv;
        }

    float* nbuf = (layer == 0) ? g_n1 : g_n2;
#pragma unroll
    for (int i = 0; i < 8; i++) {
        float ss = y[i][0] * y[i][0] + y[i][1] * y[i][1] + y[i][2] * y[i][2] + y[i][3] * y[i][3];
#pragma unroll
        for (int o = 8; o > 0; o >>= 1) ss += __shfl_xor_sync(0xffffffffu, ss, o, 16);
        float inv = 1.f / fmaxf(sqrtf(ss), 1e-12f);
        int gr = rowBase + r0 + i;
        if (gr < NC) {
            if (layer == 0)
                *(float4*)&g_ego[(size_t)gr * DD + c0] = make_float4(y[i][0], y[i][1], y[i][2], y[i][3]);
            *(float4*)&nbuf[(size_t)gr * DD + c0] =
                make_float4(y[i][0] * inv, y[i][1] * inv, y[i][2] * inv, y[i][3] * inv);
        }
    }
}

// ---------------- BPR scoring + regularization ----------------------------------
__global__ void k_score(const int* __restrict__ user, const int* __restrict__ pos,
                        const int* __restrict__ neg, const float* __restrict__ uemb,
                        const float* __restrict__ iemb) {
    __shared__ float sb[8];
    __shared__ float sr[8];
    int tid = threadIdx.x;
    int wid = tid >> 5, lane = tid & 31;
    int b = blockIdx.x * 8 + wid;
    float sp = 0.f, rg = 0.f;
    if (b < BB) {
        int uu = user[b], pp = pos[b], nn = neg[b];
        const float* u0 = uemb + (size_t)uu * DD;
        const float* p0 = iemb + (size_t)pp * DD;
        const float* n0 = iemb + (size_t)nn * DD;
        const float* u1 = g_n1 + (size_t)uu * DD;
        const float* p1 = g_n1 + (size_t)(UC + pp) * DD;
        const float* n1 = g_n1 + (size_t)(UC + nn) * DD;
        const float* u2 = g_n2 + (size_t)uu * DD;
        const float* p2 = g_n2 + (size_t)(UC + pp) * DD;
        const float* n2 = g_n2 + (size_t)(UC + nn) * DD;
        float ps = 0.f, ns = 0.f;
#pragma unroll
        for (int h = 0; h < 2; h++) {
            int d = lane + 32 * h;
            float ue = u0[d], pe = p0[d], ne = n0[d];
            rg += ue * ue + pe * pe + ne * ne;
            ps += ue * pe;
            ns += ue * ne;
            float a1 = u1[d]; ps += a1 * p1[d]; ns += a1 * n1[d];
            float a2 = u2[d]; ps += a2 * p2[d]; ns += a2 * n2[d];
        }
#pragma unroll
        for (int o = 16; o > 0; o >>= 1) {
            ps += __shfl_xor_sync(0xffffffffu, ps, o);
            ns += __shfl_xor_sync(0xffffffffu, ns, o);
            rg += __shfl_xor_sync(0xffffffffu, rg, o);
        }
        float x = ns - ps;
        sp = fmaxf(x, 0.f) + log1pf(expf(-fabsf(x)));
    }
    if (lane == 0) { sb[wid] = sp; sr[wid] = rg; }
    __syncthreads();
    if (tid == 0) {
        float s1 = 0.f, s2 = 0.f;
        for (int i = 0; i < 8; i++) { s1 += sb[i]; s2 += sr[i]; }
        atomicAdd(&g_acc[0], (double)s1);
        atomicAdd(&g_acc[1], (double)s2);
    }
}

__global__ void k_final(float* out) {
    out[0] = (float)(g_acc[0] / (double)BB);
    out[1] = (float)(0.0001 * 0.5 * g_acc[1] / (double)BB);
}

// ---------------- launch ---------------------------------------------------------
extern "C" void kernel_launch(void* const* d_in, const int* in_sizes, int n_in,
                              void* d_out, int out_size) {
    (void)in_sizes; (void)n_in; (void)out_size;
    const int*   user = (const int*)d_in[0];
    const int*   pos  = (const int*)d_in[1];
    const int*   neg  = (const int*)d_in[2];
    const int*   rows = (const int*)d_in[3];
    const int*   cols = (const int*)d_in[4];
    const float* vals = (const float*)d_in[5];
    const float* uemb = (const float*)d_in[6];
    const float* iemb = (const float*)d_in[7];
    const float* Wg0  = (const float*)d_in[8];
    const float* bg0  = (const float*)d_in[9];
    const float* Wm0  = (const float*)d_in[10];
    const float* bm0  = (const float*)d_in[11];
    const float* Wg1  = (const float*)d_in[12];
    const float* bg1  = (const float*)d_in[13];
    const float* Wm1  = (const float*)d_in[14];
    const float* bm1  = (const float*)d_in[15];
    float* out = (float*)d_out;

    float* ego = nullptr;
    cudaGetSymbolAddress((void**)&ego, g_ego);

    k_zero<<<(NC + 255) / 256, 256>>>();
    k_hist<<<1024, 256>>>(rows);
    k_scan<<<1, 1024>>>();
    k_scatter<<<2048, 256>>>(rows, cols, vals);

    int spmm_blocks = (NC * 32 + 255) / 256;
    int gemm_blocks = (NC + 127) / 128;

    // layer 0: spmm reads uemb/iemb directly (no init copy)
    k_spmm<<<spmm_blocks, 256>>>(uemb, iemb);
    k_gemm<<<gemm_blocks, 256>>>(Wg0, bg0, Wm0, bm0, 0);
    // layer 1: spmm reads g_ego
    k_spmm<<<spmm_blocks, 256>>>(ego, ego + (size_t)UC * DD);
    k_gemm<<<gemm_blocks, 256>>>(Wg1, bg1, Wm1, bm1, 1);

    k_score<<<(BB + 7) / 8, 256>>>(user, pos, neg, uemb, iemb);
    k_final<<<1, 1>>>(out);
}